// round 17
// baseline (speedup 1.0000x reference)
#include <cuda_runtime.h>
#include <cstdint>

// DbrxRouter via mma.sync tf32 (HMMA, plain-sm_100-safe) + exact refinement.
//  K0 wprep:  W fp32 -> tf32 B-fragments in mma register order (one LDS.128
//             per k8 per warp in the mainloop).
//  K1 router_mma: 128 token-tiles x 4 K-slices = 512 CTAs (single wave).
//             CTA = 128 thr / 4 warps / 64 tokens. x staged fp32 via 4-stage
//             post-barrier cp.async ring with xor swizzle; per k8: 4 LDS.32 +
//             4 cvt.tf32 (A frag), 1 LDS.128 (B frags), 2 mma. Partials to
//             glog[4][T][16].
//  K2 router_fin: warp/token: sum slices, top-5; if any adjacent gap < 2e-2
//             (~18 sigma of tf32 error) recompute logits EXACTLY in fp32.
//             Top-4 + p=1 renorm (softmax denom cancels), store.

#define NE     16
#define KSL    4             // K slices
#define TOKC   64            // tokens per CTA
#define KS     32            // floats per superchunk
#define STAGES 4
#define PRO    3
#define XSTG_B 8192          // 64 rows x 8 float4 x 16B
#define WSTG_B 2048          // 4 k8 x 32 lanes x 16B
#define TMAX   8192
#define HMAX   6144
#define THRESH 2e-2f

__device__ float    glog[KSL * TMAX * NE];
__device__ uint32_t wfrag[(HMAX / 8) * 128];   // [kc][lane][4] tf32 bits

__device__ __forceinline__ uint32_t f2tf(float f) {
    uint32_t r;
    asm("cvt.rna.tf32.f32 %0, %1;" : "=r"(r) : "f"(f));
    return r;
}
__device__ __forceinline__ void mma_tf32(float& d0, float& d1, float& d2, float& d3,
                                         uint32_t a0, uint32_t a1, uint32_t a2, uint32_t a3,
                                         uint32_t b0, uint32_t b1) {
    asm volatile("mma.sync.aligned.m16n8k8.row.col.f32.tf32.tf32.f32 "
                 "{%0,%1,%2,%3}, {%4,%5,%6,%7}, {%8,%9}, {%0,%1,%2,%3};"
                 : "+f"(d0), "+f"(d1), "+f"(d2), "+f"(d3)
                 : "r"(a0), "r"(a1), "r"(a2), "r"(a3), "r"(b0), "r"(b1));
}
__device__ __forceinline__ void cp16(uint32_t dst, const void* src) {
    asm volatile("cp.async.cg.shared.global [%0], [%1], 16;"
                 :: "r"(dst), "l"(src) : "memory");
}

// ---- K0: W fp32 -> fragment-ordered tf32 ----
__global__ __launch_bounds__(256)
void wprep(const float* __restrict__ w, int H)
{
    const int i = blockIdx.x * blockDim.x + threadIdx.x;  // (kc, lane)
    const int kc = i >> 5, l = i & 31;
    if (kc >= H / 8) return;
    const int n = l >> 2, c = l & 3, k = kc * 8 + c;
    uint4 v;
    v.x = f2tf(w[n * H + k]);
    v.y = f2tf(w[n * H + k + 4]);
    v.z = f2tf(w[(n + 8) * H + k]);
    v.w = f2tf(w[(n + 8) * H + k + 4]);
    reinterpret_cast<uint4*>(wfrag)[kc * 32 + l] = v;
}

// ---- K1: tf32 MMA mainloop ----
__global__ __launch_bounds__(128, 4)
void router_mma(const float* __restrict__ x, int T, int H4)
{
    __shared__ __align__(16) uint8_t xsm[STAGES * XSTG_B];  // 32KB
    __shared__ __align__(16) uint8_t wsm[STAGES * WSTG_B];  // 8KB

    const int tid  = threadIdx.x;
    const int wid  = tid >> 5;
    const int lane = tid & 31;
    const int gid  = lane >> 2;          // groupID (row within 8)
    const int col  = lane & 3;           // threadID_in_group
    const int ct0  = blockIdx.x * TOKC;
    const int sl   = blockIdx.y;
    const int Hs4  = H4 / KSL;           // 384 float4 per slice
    const int SC   = Hs4 / 8;            // 48 superchunks
    const int kcb0 = sl * SC * 4;        // first k8 of slice

    const float4* __restrict__ x4 = reinterpret_cast<const float4*>(x);

    // ---- producer mapping: 4 x-units (16B) + 1 w-unit per thread ----
    const uint32_t xb = (uint32_t)__cvta_generic_to_shared(xsm);
    const uint32_t wb = (uint32_t)__cvta_generic_to_shared(wsm);
    uint32_t pdst[4]; const float4* psrc[4];
    #pragma unroll
    for (int u0 = 0; u0 < 4; ++u0) {
        const int u = tid + u0 * 128, row = u >> 3, c4 = u & 7;
        pdst[u0] = xb + (uint32_t)((row * 8 + (c4 ^ (row & 7))) * 16);
        psrc[u0] = x4 + (size_t)min(ct0 + row, T - 1) * H4 + sl * Hs4 + c4;
    }
    const uint4* wsrc = reinterpret_cast<const uint4*>(wfrag) + kcb0 * 32 + tid;
    const uint32_t wdst = wb + (uint32_t)(tid * 16);

    // Prologue: stages 0..PRO-1.
    #pragma unroll
    for (int p = 0; p < PRO; ++p) {
        #pragma unroll
        for (int u0 = 0; u0 < 4; ++u0)
            cp16(pdst[u0] + (uint32_t)((p & 3) * XSTG_B), psrc[u0] + p * 8);
        cp16(wdst + (uint32_t)((p & 3) * WSTG_B), wsrc + p * 128);
        asm volatile("cp.async.commit_group;" ::: "memory");
    }

    float acc[8];
    #pragma unroll
    for (int i = 0; i < 8; ++i) acc[i] = 0.f;

    const int r0 = wid * 16 + gid;       // this lane's token rows r0, r0+8
    const char* xg = reinterpret_cast<const char*>(xsm);
    const char* wg = reinterpret_cast<const char*>(wsm);

    #pragma unroll 1
    for (int c = 0; c < SC; ++c) {
        asm volatile("cp.async.wait_group %0;" :: "n"(PRO - 1) : "memory");
        __syncthreads();
        const int cf = c + PRO;
        if (cf < SC) {
            #pragma unroll
            for (int u0 = 0; u0 < 4; ++u0)
                cp16(pdst[u0] + (uint32_t)((cf & 3) * XSTG_B), psrc[u0] + cf * 8);
            cp16(wdst + (uint32_t)((cf & 3) * WSTG_B), wsrc + cf * 128);
        }
        asm volatile("cp.async.commit_group;" ::: "memory");

        const char* xs = xg + (c & 3) * XSTG_B;
        const char* ws = wg + (c & 3) * WSTG_B;
        #pragma unroll
        for (int j = 0; j < 4; ++j) {
            // A fragment (tf32): rows r0, r0+8; cols j*8+col, +4 (xor swizzle)
            const int c4lo = ((2 * j) ^ gid) * 16;        // (r0&7)==gid
            const int c4hi = ((2 * j + 1) ^ gid) * 16;
            const int rb0 = r0 * 128, rb1 = rb0 + 8 * 128;
            const uint32_t a0 = f2tf(*(const float*)(xs + rb0 + c4lo + col * 4));
            const uint32_t a1 = f2tf(*(const float*)(xs + rb1 + c4lo + col * 4));
            const uint32_t a2 = f2tf(*(const float*)(xs + rb0 + c4hi + col * 4));
            const uint32_t a3 = f2tf(*(const float*)(xs + rb1 + c4hi + col * 4));
            const uint4 B = *(const uint4*)(ws + (j * 32 + lane) * 16);
            mma_tf32(acc[0], acc[1], acc[2], acc[3], a0, a1, a2, a3, B.x, B.y);
            mma_tf32(acc[4], acc[5], acc[6], acc[7], a0, a1, a2, a3, B.z, B.w);
        }
    }

    // D frags -> glog[sl][token][16]; disjoint writes, float2 each.
    const int tok0 = ct0 + r0, tok1 = tok0 + 8;
    float* g0 = glog + ((size_t)sl * T + tok0) * NE + 2 * col;
    float* g1 = glog + ((size_t)sl * T + tok1) * NE + 2 * col;
    *reinterpret_cast<float2*>(g0)     = make_float2(acc[0], acc[1]);
    *reinterpret_cast<float2*>(g0 + 8) = make_float2(acc[4], acc[5]);
    *reinterpret_cast<float2*>(g1)     = make_float2(acc[2], acc[3]);
    *reinterpret_cast<float2*>(g1 + 8) = make_float2(acc[6], acc[7]);
}

// ---- K2: finalize (sum slices, gap test, exact recompute, top4) ----
__global__ __launch_bounds__(256)
void router_fin(const float* __restrict__ x, const float* __restrict__ w,
                float* __restrict__ out, int T, int H4, int idx_off)
{
    const int token = (blockIdx.x * blockDim.x + threadIdx.x) >> 5;
    const int lane  = threadIdx.x & 31;
    if (token >= T) return;

    float v = 0.f;
    if (lane < NE) {
        #pragma unroll
        for (int s = 0; s < KSL; ++s)
            v += glog[((size_t)s * T + token) * NE + lane];
    }
    float mylg[NE];
    #pragma unroll
    for (int e = 0; e < NE; ++e)
        mylg[e] = __shfl_sync(0xffffffffu, v, e);

    // top-5 (stable) to measure adjacent gaps
    float t5[5]; unsigned mask = 0;
    #pragma unroll
    for (int k = 0; k < 5; ++k) {
        float best = -3.402823466e38f; int bi = 0;
        #pragma unroll
        for (int e = 0; e < NE; ++e) {
            bool ok = (((mask >> e) & 1u) == 0u) && (mylg[e] > best);
            if (ok) { best = mylg[e]; bi = e; }
        }
        t5[k] = best; mask |= (1u << bi);
    }
    const bool flag = (t5[0] - t5[1] < THRESH) || (t5[1] - t5[2] < THRESH) ||
                      (t5[2] - t5[3] < THRESH) || (t5[3] - t5[4] < THRESH);

    if (flag) {  // exact fp32 recompute of all 16 logits (warp-parallel)
        const float4* __restrict__ x4 = reinterpret_cast<const float4*>(x);
        const float4* __restrict__ w4 = reinterpret_cast<const float4*>(w);
        float a[NE];
        #pragma unroll
        for (int e = 0; e < NE; ++e) a[e] = 0.f;
        for (int i = lane; i < H4; i += 32) {
            const float4 xv = x4[(size_t)token * H4 + i];
            #pragma unroll
            for (int e = 0; e < NE; ++e) {
                const float4 wv = w4[(size_t)e * H4 + i];
                a[e] += xv.x * wv.x + xv.y * wv.y + xv.z * wv.z + xv.w * wv.w;
            }
        }
        #pragma unroll
        for (int off = 16; off >= 1; off >>= 1)
            #pragma unroll
            for (int e = 0; e < NE; ++e)
                a[e] += __shfl_xor_sync(0xffffffffu, a[e], off);
        #pragma unroll
        for (int e = 0; e < NE; ++e) mylg[e] = a[e];
    }

    if (lane == 0) {
        unsigned m2 = 0; float tw[4]; int ti[4];
        #pragma unroll
        for (int k = 0; k < 4; ++k) {
            float best = -3.402823466e38f; int bi = 0;
            #pragma unroll
            for (int e = 0; e < NE; ++e) {
                bool ok = (((m2 >> e) & 1u) == 0u) && (mylg[e] > best);
                if (ok) { best = mylg[e]; bi = e; }
            }
            tw[k] = best; ti[k] = bi; m2 |= (1u << bi);
        }
        const float mx = tw[0];
        float s = 0.f;
        #pragma unroll
        for (int k = 0; k < 4; ++k) { tw[k] = expf(tw[k] - mx); s += tw[k]; }
        const float inv = 1.0f / s;
        #pragma unroll
        for (int k = 0; k < 4; ++k) {
            out[token * 4 + k] = tw[k] * inv;
            if (idx_off >= 0) out[idx_off + token * 4 + k] = (float)ti[k];
        }
    }
}

extern "C" void kernel_launch(void* const* d_in, const int* in_sizes, int n_in,
                              void* d_out, int out_size)
{
    const float* x = (const float*)d_in[0];
    const float* w = (const float*)d_in[1];

    const int H  = in_sizes[1] / NE;     // 6144
    const int T  = in_sizes[0] / H;      // 8192
    const int H4 = H / 4;                // 1536

    const int idx_off = (out_size >= T * 8) ? (T * 4) : -1;

    wprep<<<(H / 8 * 32 + 255) / 256, 256>>>(w, H);
    router_mma<<<dim3((T + TOKC - 1) / TOKC, KSL), 128>>>(x, T, H4);
    router_fin<<<(T * 32 + 255) / 256, 256>>>(x, w, (float*)d_out, T, H4, idx_off);
}